// round 6
// baseline (speedup 1.0000x reference)
#include <cuda_runtime.h>
#include <math.h>

#define NB      1024
#define HID     128
#define DIM     16
#define NSTEPS  10

// ---------------- device globals (no allocation allowed) ----------------
__device__ float g_y [NB*DIM];
__device__ float g_ys[NB*DIM];
__device__ float g_V [NB*DIM*DIM];   // g_V[p][dir j][comp i] = J[i][j]
__device__ float g_W4T[DIM*HID];     // W4 transposed: [d][k]

__global__ void prep_kernel(const float* __restrict__ W4)
{
  int i = blockIdx.x * blockDim.x + threadIdx.x;
  if (i < HID*DIM) {
    int k = i / DIM, d = i % DIM;
    g_W4T[d*HID + k] = W4[i];
  }
}

// ---------------- per-warp workspace ----------------
struct WS {
  float dH[8][HID];     // 8 tangent rows (this warp's dirs), 4096 B
  float hJ[HID];        // primal hidden, J point
  float hS[HID];        // primal hidden, star point
  float vin[8][16];     // stage tangent input [row][comp]
  float zinJ[16];
  float zinS[16];
};
// sizeof = (1024+128+128+128+16+16)*4 = 5760 bytes, 16B-aligned fields

__device__ __forceinline__ float4 ldf4(const float* p) {
  return *reinterpret_cast<const float4*>(p);
}
__device__ __forceinline__ void stf4(float* p, float4 v) {
  *reinterpret_cast<float4*>(p) = v;
}

// activation + scaled tangent store: lane owns cols c4..c4+3
__device__ __forceinline__ void act_store(WS* ws, float pJ[4], float pS[4],
                                          float t[8][4], int c4)
{
  float g[4], hj[4], hs[4];
  #pragma unroll
  for (int j = 0; j < 4; ++j) {
    hj[j] = tanhf(pJ[j]);
    hs[j] = tanhf(pS[j]);
    g[j]  = 1.f - hj[j]*hj[j];
  }
  stf4(&ws->hJ[c4], make_float4(hj[0], hj[1], hj[2], hj[3]));
  stf4(&ws->hS[c4], make_float4(hs[0], hs[1], hs[2], hs[3]));
  #pragma unroll
  for (int r = 0; r < 8; ++r)
    stf4(&ws->dH[r][c4],
         make_float4(g[0]*t[r][0], g[1]*t[r][1], g[2]*t[r][2], g[3]*t[r][3]));
}

// fused hidden layer: primal (J,S) + 8 tangent rows; K = 128
__device__ __forceinline__ void hidden_layer(WS* ws, const float* __restrict__ W,
                                             const float* __restrict__ b, int c4)
{
  float t[8][4];
  #pragma unroll
  for (int r = 0; r < 8; ++r)
    #pragma unroll
    for (int j = 0; j < 4; ++j) t[r][j] = 0.f;
  float4 bb = ldf4(&b[c4]);
  float pJ[4] = {bb.x, bb.y, bb.z, bb.w};
  float pS[4] = {bb.x, bb.y, bb.z, bb.w};

  #pragma unroll 1
  for (int kg = 0; kg < 32; ++kg) {
    int kb = kg * 4;
    float4 w[4];
    #pragma unroll
    for (int kk = 0; kk < 4; ++kk) w[kk] = ldf4(&W[(kb+kk)*HID + c4]);
    float4 hj = ldf4(&ws->hJ[kb]);
    float4 hs = ldf4(&ws->hS[kb]);
    const float hjv[4] = {hj.x, hj.y, hj.z, hj.w};
    const float hsv[4] = {hs.x, hs.y, hs.z, hs.w};
    #pragma unroll
    for (int kk = 0; kk < 4; ++kk) {
      pJ[0] += hjv[kk]*w[kk].x; pJ[1] += hjv[kk]*w[kk].y;
      pJ[2] += hjv[kk]*w[kk].z; pJ[3] += hjv[kk]*w[kk].w;
      pS[0] += hsv[kk]*w[kk].x; pS[1] += hsv[kk]*w[kk].y;
      pS[2] += hsv[kk]*w[kk].z; pS[3] += hsv[kk]*w[kk].w;
    }
    #pragma unroll
    for (int r = 0; r < 8; ++r) {
      float4 dd = ldf4(&ws->dH[r][kb]);
      t[r][0] += dd.x*w[0].x + dd.y*w[1].x + dd.z*w[2].x + dd.w*w[3].x;
      t[r][1] += dd.x*w[0].y + dd.y*w[1].y + dd.z*w[2].y + dd.w*w[3].y;
      t[r][2] += dd.x*w[0].z + dd.y*w[1].z + dd.z*w[2].z + dd.w*w[3].z;
      t[r][3] += dd.x*w[0].w + dd.y*w[1].w + dd.z*w[2].w + dd.w*w[3].w;
    }
  }
  __syncwarp();
  act_store(ws, pJ, pS, t, c4);
  __syncwarp();
}

__global__ __launch_bounds__(128, 3)
void flow_jac_kernel(const float* __restrict__ x,  const float* __restrict__ xs,
                     const float* __restrict__ W0, const float* __restrict__ b0,
                     const float* __restrict__ W1, const float* __restrict__ b1,
                     const float* __restrict__ W2, const float* __restrict__ b2,
                     const float* __restrict__ W3, const float* __restrict__ b3,
                     const float* __restrict__ b4)
{
  extern __shared__ unsigned char smem_raw[];
  const int warp = threadIdx.x >> 5;
  const int lane = threadIdx.x & 31;
  WS* ws = reinterpret_cast<WS*>(smem_raw) + warp;

  const int p  = blockIdx.x * 2 + (warp >> 1);   // 512 blocks * 2 points
  const int hf = warp & 1;                       // dir half: rows = 8*hf + 0..7
  const int c4 = lane * 4;                       // this lane's 4 hidden cols
  const int dlane = lane & 15;                   // owned component
  const int r0 = (lane >> 4) * 4;                // local tangent rows r0..r0+3
  const bool isJ = (lane < 16);

  // persistent register state
  float z = isJ ? x[p*DIM + dlane] : xs[p*DIM + dlane];  // own trajectory comp
  float v[4], u[4], kst = 0.f;
  #pragma unroll
  for (int rr = 0; rr < 4; ++rr) {
    v[rr] = ((8*hf + r0 + rr) == dlane) ? 1.f : 0.f;
    u[rr] = 0.f;
  }

  const float dt = 1.f / NSTEPS;
  const float f6 = dt / 6.f;
  const float b4d = b4[dlane];

  for (int step = 0; step < NSTEPS; ++step) {
    const float t0 = step * dt;
    float ksum = 0.f, usum[4] = {0.f, 0.f, 0.f, 0.f};

    for (int s = 0; s < 4; ++s) {
      const float cs  = (s == 0) ? 0.f : ((s == 3) ? dt : 0.5f * dt);
      const float ts  = t0 + cs;
      const float wgt = (s == 0 || s == 3) ? 1.f : 2.f;

      // ---- stage inputs ----
      float zin = z + cs * kst;
      if (isJ) ws->zinJ[dlane] = zin; else ws->zinS[dlane] = zin;
      #pragma unroll
      for (int rr = 0; rr < 4; ++rr)
        ws->vin[r0 + rr][dlane] = v[rr] + cs * u[rr];
      __syncwarp();

      // ================= layer 0 (K=16 + t row), fused primal+tangent ========
      {
        float t[8][4];
        #pragma unroll
        for (int r = 0; r < 8; ++r)
          #pragma unroll
          for (int j = 0; j < 4; ++j) t[r][j] = 0.f;
        float4 bb = ldf4(&b0[c4]);
        float pJ[4] = {bb.x, bb.y, bb.z, bb.w};
        float pS[4] = {bb.x, bb.y, bb.z, bb.w};

        #pragma unroll
        for (int kg = 0; kg < 4; ++kg) {
          int kb = kg * 4;
          float4 w[4];
          #pragma unroll
          for (int kk = 0; kk < 4; ++kk) w[kk] = ldf4(&W0[(kb+kk)*HID + c4]);
          float4 zj = ldf4(&ws->zinJ[kb]);
          float4 zs4 = ldf4(&ws->zinS[kb]);
          const float zjv[4] = {zj.x, zj.y, zj.z, zj.w};
          const float zsv[4] = {zs4.x, zs4.y, zs4.z, zs4.w};
          #pragma unroll
          for (int kk = 0; kk < 4; ++kk) {
            pJ[0] += zjv[kk]*w[kk].x; pJ[1] += zjv[kk]*w[kk].y;
            pJ[2] += zjv[kk]*w[kk].z; pJ[3] += zjv[kk]*w[kk].w;
            pS[0] += zsv[kk]*w[kk].x; pS[1] += zsv[kk]*w[kk].y;
            pS[2] += zsv[kk]*w[kk].z; pS[3] += zsv[kk]*w[kk].w;
          }
          #pragma unroll
          for (int r = 0; r < 8; ++r) {
            float4 dd = ldf4(&ws->vin[r][kb]);
            t[r][0] += dd.x*w[0].x + dd.y*w[1].x + dd.z*w[2].x + dd.w*w[3].x;
            t[r][1] += dd.x*w[0].y + dd.y*w[1].y + dd.z*w[2].y + dd.w*w[3].y;
            t[r][2] += dd.x*w[0].z + dd.y*w[1].z + dd.z*w[2].z + dd.w*w[3].z;
            t[r][3] += dd.x*w[0].w + dd.y*w[1].w + dd.z*w[2].w + dd.w*w[3].w;
          }
        }
        // time row (primal only; tangent of t is zero)
        float4 wt = ldf4(&W0[16*HID + c4]);
        pJ[0] += ts*wt.x; pJ[1] += ts*wt.y; pJ[2] += ts*wt.z; pJ[3] += ts*wt.w;
        pS[0] += ts*wt.x; pS[1] += ts*wt.y; pS[2] += ts*wt.z; pS[3] += ts*wt.w;

        __syncwarp();   // all lanes done reading hJ/hS/dH of previous stage
        act_store(ws, pJ, pS, t, c4);
        __syncwarp();
      }

      // ================= hidden layers 1..3 =================
      hidden_layer(ws, W1, b1, c4);
      hidden_layer(ws, W2, b2, c4);
      hidden_layer(ws, W3, b3, c4);

      // ================= output layer (K=128 -> 16) =========================
      {
        float o[4] = {0.f, 0.f, 0.f, 0.f};
        float pa = 0.f;
        const float* hb = isJ ? ws->hJ : ws->hS;
        const float* w4row = g_W4T + dlane*HID;
        #pragma unroll 1
        for (int kg = 0; kg < 32; ++kg) {
          int kb = kg * 4;
          float4 h4 = ldf4(&hb[kb]);
          float4 w4 = ldf4(&w4row[kb]);
          pa += h4.x*w4.x + h4.y*w4.y + h4.z*w4.z + h4.w*w4.w;
          #pragma unroll
          for (int rr = 0; rr < 4; ++rr) {
            float4 dd = ldf4(&ws->dH[r0+rr][kb]);
            o[rr] += dd.x*w4.x + dd.y*w4.y + dd.z*w4.z + dd.w*w4.w;
          }
        }
        kst = pa + b4d;
        ksum += wgt * kst;
        #pragma unroll
        for (int rr = 0; rr < 4; ++rr) {
          u[rr] = o[rr];
          usum[rr] += wgt * o[rr];
        }
      }
    } // stages

    // RK4 update
    z += f6 * ksum;
    #pragma unroll
    for (int rr = 0; rr < 4; ++rr) v[rr] += f6 * usum[rr];
  } // steps

  // ---- write results ----
  if (isJ) g_y [p*DIM + dlane] = z;
  else     g_ys[p*DIM + dlane] = z;
  #pragma unroll
  for (int rr = 0; rr < 4; ++rr)
    g_V[p*256 + (8*hf + r0 + rr)*16 + dlane] = v[rr];
}

// =========================== finalize (unchanged, verified) ===========================
__global__ void finalize_kernel(float* __restrict__ out)
{
  int p = blockIdx.x * blockDim.x + threadIdx.x;
  if (p >= NB) return;

  float gph[16]; float n2 = 0.f;
  #pragma unroll
  for (int i = 0; i < 16; ++i) {
    float dd = g_y[p*DIM + i] - g_ys[p*DIM + i];
    gph[i] = dd; n2 += dd * dd;
  }
  float inv = 1.f / (sqrtf(n2) + 1e-8f);
  #pragma unroll
  for (int i = 0; i < 16; ++i) gph[i] *= inv;

  float Vr[16][16];
  const float* V = g_V + p * 256;
  for (int j = 0; j < 16; ++j)
    for (int i = 0; i < 16; ++i) Vr[j][i] = V[j*16 + i];

  float gx[16];
  for (int j = 0; j < 16; ++j) {
    float sacc = 0.f;
    for (int i = 0; i < 16; ++i) sacc += Vr[j][i] * gph[i];
    gx[j] = sacc;
  }

  float G[16][16];
  for (int j = 0; j < 16; ++j)
    for (int k = 0; k <= j; ++k) {
      float sacc = 0.f;
      for (int i = 0; i < 16; ++i) sacc += Vr[j][i] * Vr[k][i];
      G[j][k] = sacc; G[k][j] = sacc;
    }
  for (int j = 0; j < 16; ++j) G[j][j] += 1e-6f;

  for (int j = 0; j < 16; ++j) {
    float dd = G[j][j];
    for (int k = 0; k < j; ++k) dd -= G[j][k] * G[j][k];
    dd = sqrtf(fmaxf(dd, 1e-30f));
    G[j][j] = dd;
    float id = 1.f / dd;
    for (int i = j + 1; i < 16; ++i) {
      float sacc = G[i][j];
      for (int k = 0; k < j; ++k) sacc -= G[i][k] * G[j][k];
      G[i][j] = sacc * id;
    }
  }
  float yv[16];
  for (int i = 0; i < 16; ++i) {
    float sacc = gx[i];
    for (int k = 0; k < i; ++k) sacc -= G[i][k] * yv[k];
    yv[i] = sacc / G[i][i];
  }
  float sol[16];
  for (int i = 15; i >= 0; --i) {
    float sacc = yv[i];
    for (int k = i + 1; k < 16; ++k) sacc -= G[k][i] * sol[k];
    sol[i] = sacc / G[i][i];
  }
  for (int j = 0; j < 16; ++j) out[p*DIM + j] = -sol[j];
}

extern "C" void kernel_launch(void* const* d_in, const int* in_sizes, int n_in,
                              void* d_out, int out_size)
{
  const float* x  = (const float*)d_in[0];
  const float* xs = (const float*)d_in[1];
  const float* W0 = (const float*)d_in[2];
  const float* b0 = (const float*)d_in[3];
  const float* W1 = (const float*)d_in[4];
  const float* b1 = (const float*)d_in[5];
  const float* W2 = (const float*)d_in[6];
  const float* b2 = (const float*)d_in[7];
  const float* W3 = (const float*)d_in[8];
  const float* b3 = (const float*)d_in[9];
  const float* W4 = (const float*)d_in[10];
  const float* b4 = (const float*)d_in[11];
  float* out = (float*)d_out;

  prep_kernel<<<8, 256>>>(W4);

  size_t sh = sizeof(WS) * 4;   // 5760 * 4 = 23040 bytes per CTA
  cudaFuncSetAttribute(flow_jac_kernel, cudaFuncAttributeMaxDynamicSharedMemorySize, (int)sh);
  flow_jac_kernel<<<512, 128, sh>>>(x, xs, W0, b0, W1, b1, W2, b2, W3, b3, b4);
  finalize_kernel<<<8, 128>>>(out);
}

// round 8
// speedup vs baseline: 4.5258x; 4.5258x over previous
#include <cuda_runtime.h>
#include <cuda_fp16.h>
#include <math.h>

#define NB 1024
#define NSTEPS 10
typedef unsigned int u32;

#define STR   272
#define WHALF 34816
#define WBYTES 69632
#define S_A0  0
#define S_A1  39168
#define S_W   78336
#define S_G   217600
#define S_TOT 221696

__device__ float g_y[NB*16], g_ys[NB*16], g_V[NB*256];
__device__ __align__(16) __half g_Wt[5][34816];   // per layer: hi[128][136], lo[128][136]

__global__ void prep(const float* __restrict__ W0, const float* __restrict__ W1,
                     const float* __restrict__ W2, const float* __restrict__ W3,
                     const float* __restrict__ W4)
{
  int i = blockIdx.x*256 + threadIdx.x;
  if (i >= 5*128*136) return;
  int l = i/(128*136), r = i%(128*136), n = r/136, k = r%136;
  float w = 0.f;
  if (l==0){ if (k<17) w = W0[k*128+n]; }
  else if (l==4){ if (n<16 && k<128) w = W4[k*16+n]; }
  else { const float* W = (l==1)?W1:(l==2)?W2:W3; if (k<128) w = W[k*128+n]; }
  __half h = __float2half_rn(w);
  g_Wt[l][n*136+k] = h;
  g_Wt[l][17408 + n*136+k] = __float2half_rn(w - __half2float(h));
}

__device__ __forceinline__ u32 s2u(const void* p){ u32 a;
  asm("{.reg .u64 t; cvta.to.shared.u64 t,%1; cvt.u32.u64 %0,t;}":"=r"(a):"l"(p)); return a; }
__device__ __forceinline__ void ldm4(u32 a, u32 r[4]){
  asm volatile("ldmatrix.sync.aligned.m8n8.x4.shared.b16 {%0,%1,%2,%3},[%4];"
    :"=r"(r[0]),"=r"(r[1]),"=r"(r[2]),"=r"(r[3]):"r"(a)); }
__device__ __forceinline__ void mmaop(float d[4], const u32 a[4], u32 b0, u32 b1){
  asm volatile("mma.sync.aligned.m16n8k16.row.col.f32.f16.f16.f32 "
    "{%0,%1,%2,%3},{%4,%5,%6,%7},{%8,%9},{%0,%1,%2,%3};"
    :"+f"(d[0]),"+f"(d[1]),"+f"(d[2]),"+f"(d[3])
    :"r"(a[0]),"r"(a[1]),"r"(a[2]),"r"(a[3]),"r"(b0),"r"(b1)); }
#define CPASYNC(dst,src) asm volatile("cp.async.cg.shared.global [%0],[%1],16;"::"r"(dst),"l"(src):"memory")
#define CPCOMMIT() asm volatile("cp.async.commit_group;":::"memory")
#define CPWAIT()   asm volatile("cp.async.wait_group 0;":::"memory")

__device__ __forceinline__ void sts2(char* sm, u32 o, float a, float b){
  __half ha=__float2half_rn(a), hb=__float2half_rn(b);
  __half la=__float2half_rn(a-__half2float(ha)), lb=__float2half_rn(b-__half2float(hb));
  *(__half2*)(sm + S_A0 + o) = __halves2half2(ha,hb);
  *(__half2*)(sm + S_A1 + o) = __halves2half2(la,lb);
}

__global__ __launch_bounds__(256,1)
void flow(const float* __restrict__ x,  const float* __restrict__ xs,
          const float* __restrict__ b0, const float* __restrict__ b1,
          const float* __restrict__ b2, const float* __restrict__ b3,
          const float* __restrict__ b4)
{
  extern __shared__ char sm[];
  const u32 sb = s2u(sm);
  const int tid = threadIdx.x, w = tid>>5, l = tid&31;
  const int P0 = blockIdx.x*8;
  const int mb = w&3, nb = w>>2;
  const int lr = l>>2, lc2 = (l&3)*2;

  const u32 offA = (u32)(l&15)*STR + (u32)(l>>4)*16;
  const u32 offB = ((u32)(l&7) + ((u32)(l>>4)&1)*8)*STR + (((u32)l>>3)&1)*16;

  // fragment-layout register state
  float v[2][4], uu[2][4], usum[2][4], zz[2][4], kst[2][4], ksum[2][4];
  #pragma unroll
  for (int nf=0; nf<2; ++nf)
    #pragma unroll
    for (int r=0; r<4; ++r){
      int dir = lr + ((r>=2)?8:0), comp = nf*8 + lc2 + (r&1);
      v[nf][r] = (dir==comp)?1.f:0.f; uu[nf][r]=0.f;
      zz[nf][r]=0.f; kst[nf][r]=0.f;
    }
  if (w==4){
    #pragma unroll
    for (int nf=0; nf<2; ++nf){
      int n = nf*8 + lc2;
      zz[nf][0] = x [(P0+lr)*16 + n];   zz[nf][1] = x [(P0+lr)*16 + n+1];
      zz[nf][2] = xs[(P0+lr)*16 + n];   zz[nf][3] = xs[(P0+lr)*16 + n+1];
    }
  }

  // initial W prefetch: slot 0 -> buf 0
  {
    const char* src = (const char*)g_Wt[0];
    u32 dst = sb + S_W;
    for (int i=tid; i<WBYTES/16; i+=256) CPASYNC(dst + i*16, src + i*16);
    CPCOMMIT();
  }
  int wp = 0;
  const float dt = 1.f/NSTEPS, f6 = dt/6.f;

  for (int step=0; step<NSTEPS; ++step){
    const float t0 = step*dt;
    #pragma unroll
    for (int nf=0; nf<2; ++nf)
      #pragma unroll
      for (int r=0; r<4; ++r){ usum[nf][r]=0.f; ksum[nf][r]=0.f; }

    for (int s=0; s<4; ++s){
      const float cs = (s==0)?0.f:((s==3)?dt:0.5f*dt);
      const float ts = t0+cs, wgt = (s==0||s==3)?1.f:2.f;

      // ---- stage inputs into A tiles ----
      #pragma unroll
      for (int nf=0; nf<2; ++nf){
        int n = nf*8 + lc2;
        sts2(sm, (u32)((w*16+lr  )*STR + n*2), v[nf][0]+cs*uu[nf][0], v[nf][1]+cs*uu[nf][1]);
        sts2(sm, (u32)((w*16+lr+8)*STR + n*2), v[nf][2]+cs*uu[nf][2], v[nf][3]+cs*uu[nf][3]);
      }
      if (w==4){
        #pragma unroll
        for (int nf=0; nf<2; ++nf){
          int n = nf*8 + lc2;
          sts2(sm, (u32)((128+lr)*STR + n*2), zz[nf][0]+cs*kst[nf][0], zz[nf][1]+cs*kst[nf][1]);
          sts2(sm, (u32)((136+lr)*STR + n*2), zz[nf][2]+cs*kst[nf][2], zz[nf][3]+cs*kst[nf][3]);
        }
        if (l<16){
          int row = 128+l; uint4 z4 = make_uint4(0,0,0,0);
          *(uint4*)(sm + S_A0 + row*STR + 32) = z4; *(uint4*)(sm + S_A0 + row*STR + 48) = z4;
          *(uint4*)(sm + S_A1 + row*STR + 32) = z4; *(uint4*)(sm + S_A1 + row*STR + 48) = z4;
        }
        __syncwarp();
        if (l<16){
          int row = 128+l;
          __half th = __float2half_rn(ts);
          *(__half*)(sm + S_A0 + row*STR + 32) = th;
          *(__half*)(sm + S_A1 + row*STR + 32) = __float2half_rn(ts - __half2float(th));
        }
      }

      for (int ly=0; ly<5; ++ly){
        CPWAIT();
        __syncthreads();   // W[ly] ready; A writes visible
        // prefetch next layer (skip at very end of kernel)
        if (!(step==NSTEPS-1 && s==3 && ly==4)){
          const char* src = (const char*)g_Wt[(ly+1)%5];
          u32 dst = sb + S_W + (u32)(wp^1)*WBYTES;
          for (int i=tid; i<WBYTES/16; i+=256) CPASYNC(dst + i*16, src + i*16);
          CPCOMMIT();
        }
        const u32 wbh = sb + S_W + (u32)wp*WBYTES, wbl = wbh + WHALF;

        if (ly<4){
          float Dt[2][8][4], Dp[2][4];
          #pragma unroll
          for (int mf=0; mf<2; ++mf)
            #pragma unroll
            for (int nf=0; nf<8; ++nf)
              #pragma unroll
              for (int r=0; r<4; ++r) Dt[mf][nf][r]=0.f;
          #pragma unroll
          for (int nf=0; nf<2; ++nf)
            #pragma unroll
            for (int r=0; r<4; ++r) Dp[nf][r]=0.f;

          const int KCfull = ly?8:2, KCt = ly?8:1;
          #pragma unroll 1
          for (int kc=0; kc<KCfull; ++kc){
            const u32 kb = (u32)kc*32;
            u32 Aph[4], Apl[4];
            ldm4(sb + S_A0 + 128*STR + kb + offA, Aph);
            ldm4(sb + S_A1 + 128*STR + kb + offA, Apl);
            u32 Ah[2][4], Al[2][4];
            const bool doT = (kc < KCt);
            if (doT){
              ldm4(sb + S_A0 + (mb*32   )*STR + kb + offA, Ah[0]);
              ldm4(sb + S_A0 + (mb*32+16)*STR + kb + offA, Ah[1]);
              ldm4(sb + S_A1 + (mb*32   )*STR + kb + offA, Al[0]);
              ldm4(sb + S_A1 + (mb*32+16)*STR + kb + offA, Al[1]);
            }
            #pragma unroll
            for (int g=0; g<4; ++g){
              u32 Bh[4], Bl[4];
              ldm4(wbh + (u32)(nb*64+g*16)*STR + kb + offB, Bh);
              ldm4(wbl + (u32)(nb*64+g*16)*STR + kb + offB, Bl);
              if (doT){
                #pragma unroll
                for (int mf=0; mf<2; ++mf){
                  mmaop(Dt[mf][g*2  ], Ah[mf], Bh[0],Bh[1]);
                  mmaop(Dt[mf][g*2  ], Al[mf], Bh[0],Bh[1]);
                  mmaop(Dt[mf][g*2  ], Ah[mf], Bl[0],Bl[1]);
                  mmaop(Dt[mf][g*2+1], Ah[mf], Bh[2],Bh[3]);
                  mmaop(Dt[mf][g*2+1], Al[mf], Bh[2],Bh[3]);
                  mmaop(Dt[mf][g*2+1], Ah[mf], Bl[2],Bl[3]);
                }
              }
              if (g==mb){   // this warp's primal n-slice = cols w*16.. = nb*64 + mb*16
                mmaop(Dp[0], Aph, Bh[0],Bh[1]); mmaop(Dp[0], Apl, Bh[0],Bh[1]); mmaop(Dp[0], Aph, Bl[0],Bl[1]);
                mmaop(Dp[1], Aph, Bh[2],Bh[3]); mmaop(Dp[1], Apl, Bh[2],Bh[3]); mmaop(Dp[1], Aph, Bl[2],Bl[3]);
              }
            }
          }
          __syncthreads();   // all mma reads of A done
          // epilogue phase 1: primal (bias + tanh), record g for J rows
          const float* bias = (ly==0)?b0:(ly==1)?b1:(ly==2)?b2:b3;
          #pragma unroll
          for (int nf=0; nf<2; ++nf){
            int n = w*16 + nf*8 + lc2;
            float bx = bias[n], by = bias[n+1];
            float h0=tanhf(Dp[nf][0]+bx), h1=tanhf(Dp[nf][1]+by);
            float h2=tanhf(Dp[nf][2]+bx), h3=tanhf(Dp[nf][3]+by);
            sts2(sm, (u32)((128+lr)*STR + n*2), h0, h1);
            sts2(sm, (u32)((136+lr)*STR + n*2), h2, h3);
            *(float2*)(sm + S_G + lr*512 + n*4) = make_float2(1.f-h0*h0, 1.f-h1*h1);
          }
          __syncthreads();
          // epilogue phase 2: tangent (scale by g), write next A
          #pragma unroll
          for (int mf=0; mf<2; ++mf){
            int p = mb*2 + mf;
            #pragma unroll
            for (int nf=0; nf<8; ++nf){
              int n = nb*64 + nf*8 + lc2;
              float2 gv = *(float2*)(sm + S_G + p*512 + n*4);
              int r0 = mb*32 + mf*16 + lr;
              sts2(sm, (u32)(r0*STR + n*2),     Dt[mf][nf][0]*gv.x, Dt[mf][nf][1]*gv.y);
              sts2(sm, (u32)((r0+8)*STR + n*2), Dt[mf][nf][2]*gv.x, Dt[mf][nf][3]*gv.y);
            }
          }
        } else {
          // L4: D[144][16]; warp w -> point w's dirs; warp 4 also primal
          float D4[2][4], Dp4[2][4];
          #pragma unroll
          for (int nf=0; nf<2; ++nf)
            #pragma unroll
            for (int r=0; r<4; ++r){ D4[nf][r]=0.f; Dp4[nf][r]=0.f; }
          #pragma unroll 1
          for (int kc=0; kc<8; ++kc){
            const u32 kb = (u32)kc*32;
            u32 Ah[4], Al[4], Bh[4], Bl[4];
            ldm4(sb + S_A0 + (w*16)*STR + kb + offA, Ah);
            ldm4(sb + S_A1 + (w*16)*STR + kb + offA, Al);
            ldm4(wbh + kb + offB, Bh);
            ldm4(wbl + kb + offB, Bl);
            mmaop(D4[0],Ah,Bh[0],Bh[1]); mmaop(D4[0],Al,Bh[0],Bh[1]); mmaop(D4[0],Ah,Bl[0],Bl[1]);
            mmaop(D4[1],Ah,Bh[2],Bh[3]); mmaop(D4[1],Al,Bh[2],Bh[3]); mmaop(D4[1],Ah,Bl[2],Bl[3]);
            if (w==4){
              u32 Ap[4], Apl[4];
              ldm4(sb + S_A0 + 128*STR + kb + offA, Ap);
              ldm4(sb + S_A1 + 128*STR + kb + offA, Apl);
              mmaop(Dp4[0],Ap,Bh[0],Bh[1]); mmaop(Dp4[0],Apl,Bh[0],Bh[1]); mmaop(Dp4[0],Ap,Bl[0],Bl[1]);
              mmaop(Dp4[1],Ap,Bh[2],Bh[3]); mmaop(Dp4[1],Apl,Bh[2],Bh[3]); mmaop(Dp4[1],Ap,Bl[2],Bl[3]);
            }
          }
          __syncthreads();   // A reads done before next stage-input writes
          #pragma unroll
          for (int nf=0; nf<2; ++nf)
            #pragma unroll
            for (int r=0; r<4; ++r){ uu[nf][r]=D4[nf][r]; usum[nf][r]+=wgt*D4[nf][r]; }
          if (w==4){
            #pragma unroll
            for (int nf=0; nf<2; ++nf){
              int n = nf*8 + lc2;
              kst[nf][0]=Dp4[nf][0]+b4[n]; kst[nf][1]=Dp4[nf][1]+b4[n+1];
              kst[nf][2]=Dp4[nf][2]+b4[n]; kst[nf][3]=Dp4[nf][3]+b4[n+1];
              #pragma unroll
              for (int r=0; r<4; ++r) ksum[nf][r]+=wgt*kst[nf][r];
            }
          }
        }
        wp ^= 1;
      } // layers
    } // stages

    #pragma unroll
    for (int nf=0; nf<2; ++nf)
      #pragma unroll
      for (int r=0; r<4; ++r){ v[nf][r] += f6*usum[nf][r]; zz[nf][r] += f6*ksum[nf][r]; }
  } // steps

  // outputs
  #pragma unroll
  for (int nf=0; nf<2; ++nf)
    #pragma unroll
    for (int r=0; r<4; ++r){
      int dir = lr + ((r>=2)?8:0), comp = nf*8 + lc2 + (r&1);
      g_V[(P0+w)*256 + dir*16 + comp] = v[nf][r];
    }
  if (w==4){
    #pragma unroll
    for (int nf=0; nf<2; ++nf){
      int n = nf*8 + lc2;
      g_y [(P0+lr)*16 + n  ] = zz[nf][0];
      g_y [(P0+lr)*16 + n+1] = zz[nf][1];
      g_ys[(P0+lr)*16 + n  ] = zz[nf][2];
      g_ys[(P0+lr)*16 + n+1] = zz[nf][3];
    }
  }
}

// =========================== finalize (unchanged, verified) ===========================
__global__ void finalize_kernel(float* __restrict__ out)
{
  int p = blockIdx.x*blockDim.x + threadIdx.x;
  if (p >= NB) return;
  float gph[16], n2=0.f;
  for (int i=0;i<16;++i){ float d=g_y[p*16+i]-g_ys[p*16+i]; gph[i]=d; n2+=d*d; }
  float inv=1.f/(sqrtf(n2)+1e-8f);
  for (int i=0;i<16;++i) gph[i]*=inv;
  float Vr[16][16]; const float* V=g_V+p*256;
  for (int j=0;j<16;++j) for (int i=0;i<16;++i) Vr[j][i]=V[j*16+i];
  float gx[16];
  for (int j=0;j<16;++j){ float s=0.f; for (int i=0;i<16;++i) s+=Vr[j][i]*gph[i]; gx[j]=s; }
  float G[16][16];
  for (int j=0;j<16;++j) for (int k=0;k<=j;++k){
    float s=0.f; for (int i=0;i<16;++i) s+=Vr[j][i]*Vr[k][i]; G[j][k]=s; G[k][j]=s; }
  for (int j=0;j<16;++j) G[j][j]+=1e-6f;
  for (int j=0;j<16;++j){
    float d=G[j][j]; for (int k=0;k<j;++k) d-=G[j][k]*G[j][k];
    d=sqrtf(fmaxf(d,1e-30f)); G[j][j]=d; float id=1.f/d;
    for (int i=j+1;i<16;++i){ float s=G[i][j];
      for (int k=0;k<j;++k) s-=G[i][k]*G[j][k]; G[i][j]=s*id; } }
  float yv[16];
  for (int i=0;i<16;++i){ float s=gx[i];
    for (int k=0;k<i;++k) s-=G[i][k]*yv[k]; yv[i]=s/G[i][i]; }
  float sol[16];
  for (int i=15;i>=0;--i){ float s=yv[i];
    for (int k=i+1;k<16;++k) s-=G[k][i]*sol[k]; sol[i]=s/G[i][i]; }
  for (int j=0;j<16;++j) out[p*16+j]=-sol[j];
}

extern "C" void kernel_launch(void* const* d_in, const int* in_sizes, int n_in,
                              void* d_out, int out_size)
{
  const float* x  = (const float*)d_in[0];
  const float* xs = (const float*)d_in[1];
  const float* W0 = (const float*)d_in[2];
  const float* b0 = (const float*)d_in[3];
  const float* W1 = (const float*)d_in[4];
  const float* b1 = (const float*)d_in[5];
  const float* W2 = (const float*)d_in[6];
  const float* b2 = (const float*)d_in[7];
  const float* W3 = (const float*)d_in[8];
  const float* b3 = (const float*)d_in[9];
  const float* W4 = (const float*)d_in[10];
  const float* b4 = (const float*)d_in[11];
  float* out = (float*)d_out;

  prep<<<340,256>>>(W0,W1,W2,W3,W4);
  cudaFuncSetAttribute(flow, cudaFuncAttributeMaxDynamicSharedMemorySize, S_TOT);
  flow<<<128,256,S_TOT>>>(x,xs,b0,b1,b2,b3,b4);
  finalize_kernel<<<8,128>>>(out);
}